// round 1
// baseline (speedup 1.0000x reference)
#include <cuda_runtime.h>
#include <cuda_bf16.h>
#include <cstdint>
#include <cstddef>

// ---------------------------------------------------------------------------
// HierarchicalMemoryWorker — fused fp32 implementation (round 1)
//
// Shapes: B=2,S=1024 (T=2048 tokens), V=32000, E=512, N=8, M=2048, KD=VD=32, K=4
//
// K1: embed gather + sector softmax + token query
// K2: score GEMM (x_emb @ memory_keys^T) with streaming top-4 + weights
//     (uses fma.rn.f32x2 packed math: 2 MACs/instr -> 128 FMA/SM/cyc)
// K3: knowledge gather + matvec + sector mix + Wo proj + residual + LayerNorm
// ---------------------------------------------------------------------------

#define NTOK   2048
#define EDIM   512
#define NSEC   8
#define MTOT   2048
#define KDIM   32
#define VDIM   32
#define TOPK   4

// K2 tiling
#define TT   128      // token tile
#define MT   128      // memory chunk
#define KC   16       // k chunk
#define LDT  132      // smem row stride (floats), 16B-aligned, conflict-softened

#define SMEM2_FLOATS ((2*KC + TT) * LDT)
#define SMEM2_BYTES  (SMEM2_FLOATS * 4)   // 84480 bytes

// scratch (device globals: no allocation allowed)
__device__ float g_xe[NTOK * EDIM];        // 4 MB
__device__ float g_tq[NTOK * KDIM];        // 256 KB
__device__ float g_w [NTOK * NSEC * TOPK]; // 256 KB
__device__ int   g_ix[NTOK * NSEC * TOPK]; // 256 KB

// packed f32x2 helpers
#define PACK_DUP(d, f) asm("mov.b64 %0, {%1, %1};" : "=l"(d) : "r"(__float_as_uint(f)))
#define FMA2(c, a, b)  asm("fma.rn.f32x2 %0, %1, %2, %0;" : "+l"(c) : "l"(a), "l"(b))

// ---------------------------------------------------------------------------
// K1: per-token embed gather, sector scores->softmax, token query
// grid: NTOK blocks, 128 threads
// ---------------------------------------------------------------------------
__global__ __launch_bounds__(128) void k1_embed(
    const int* __restrict__ x,
    const float* __restrict__ emb,
    const float* __restrict__ skeys,   // [N][E]
    const float* __restrict__ Wq,      // [E][KD]
    const float* __restrict__ bq,      // [KD]
    float* __restrict__ outSD)         // [NTOK][N]
{
    const int t   = blockIdx.x;
    const int tid = threadIdx.x;
    const int lane = tid & 31;
    const int wid  = tid >> 5;

    __shared__ float se[EDIM];
    __shared__ float sred[NSEC][4];
    __shared__ float ssc[NSEC];

    const int xi = x[t];
    float4 ev = *(const float4*)&emb[(size_t)xi * EDIM + tid * 4];
    *(float4*)&g_xe[(size_t)t * EDIM + tid * 4] = ev;
    *(float4*)&se[tid * 4] = ev;

    float p[NSEC];
#pragma unroll
    for (int n = 0; n < NSEC; n++) {
        float4 kv = *(const float4*)&skeys[n * EDIM + tid * 4];
        p[n] = ev.x * kv.x + ev.y * kv.y + ev.z * kv.z + ev.w * kv.w;
    }
#pragma unroll
    for (int n = 0; n < NSEC; n++)
#pragma unroll
        for (int o = 16; o > 0; o >>= 1)
            p[n] += __shfl_xor_sync(0xffffffffu, p[n], o);
    if (lane == 0) {
#pragma unroll
        for (int n = 0; n < NSEC; n++) sred[n][wid] = p[n];
    }
    __syncthreads();
    if (tid == 0) {
        float s[NSEC];
        float mx = -1e30f;
#pragma unroll
        for (int n = 0; n < NSEC; n++) {
            s[n] = sred[n][0] + sred[n][1] + sred[n][2] + sred[n][3];
            mx = fmaxf(mx, s[n]);
        }
        float sum = 0.f;
#pragma unroll
        for (int n = 0; n < NSEC; n++) { s[n] = expf(s[n] - mx); sum += s[n]; }
#pragma unroll
        for (int n = 0; n < NSEC; n++) {
            float d = s[n] / sum;
            ssc[n] = d;
            outSD[t * NSEC + n] = d;
        }
    }
    __syncthreads();
    (void)ssc;

    // token query: 32 outputs
    if (tid < KDIM) {
        float acc = bq[tid];
#pragma unroll 8
        for (int j = 0; j < EDIM; j++)
            acc += se[j] * Wq[j * KDIM + tid];
        g_tq[t * KDIM + tid] = acc;
    }
}

// ---------------------------------------------------------------------------
// K2: score GEMM + streaming top-4
// grid: (NTOK/TT, NSEC), 256 threads
// thread (tx = tid&15, ty = tid>>4) computes an 8x8 (tok x mem) register tile
// as 8x4 f32x2 pairs.
// ---------------------------------------------------------------------------
__global__ __launch_bounds__(256, 1) void k2_scores(
    const float* __restrict__ mkeys)   // [N][M][E]
{
    extern __shared__ float sm[];
    float* sA = sm;                    // [KC][LDT]  (k-major, token minor)
    float* sB = sm + KC * LDT;         // [KC][LDT]  (k-major, mem minor)
    float* sS = sm + 2 * KC * LDT;     // [TT][LDT]  score tile

    const int tid = threadIdx.x;
    const int tb  = blockIdx.x * TT;
    const int n   = blockIdx.y;
    const int tx  = tid & 15;
    const int ty  = tid >> 4;

    // global load mapping: 512 float4 per tile, 2 per thread
    const int idx0 = tid, idx1 = tid + 256;
    const int r0 = idx0 >> 2, c0 = (idx0 & 3) * 4;
    const int r1 = idx1 >> 2, c1 = (idx1 & 3) * 4;

    const float* Ab0 = &g_xe[(size_t)(tb + r0) * EDIM + c0];
    const float* Ab1 = &g_xe[(size_t)(tb + r1) * EDIM + c1];
    const float* Bn  = mkeys + (size_t)n * MTOT * EDIM;

    // persistent top-4 state (tid < TT owns token tb+tid)
    float v0 = -1e30f, v1 = -1e30f, v2 = -1e30f, v3 = -1e30f;
    int   i0 = 0, i1 = 0, i2 = 0, i3 = 0;

    for (int mb = 0; mb < MTOT; mb += MT) {
        unsigned long long acc[32];
#pragma unroll
        for (int i = 0; i < 32; i++) acc[i] = 0ull;

        const float* Bb0 = Bn + (size_t)(mb + r0) * EDIM + c0;
        const float* Bb1 = Bn + (size_t)(mb + r1) * EDIM + c1;

        float4 a0v = *(const float4*)(Ab0);
        float4 a1v = *(const float4*)(Ab1);
        float4 b0v = *(const float4*)(Bb0);
        float4 b1v = *(const float4*)(Bb1);

        for (int kc = 0; kc < EDIM; kc += KC) {
            __syncthreads();   // previous compute / scan done
            // store prefetched regs to smem (transposed)
            sA[(c0 + 0) * LDT + r0] = a0v.x;
            sA[(c0 + 1) * LDT + r0] = a0v.y;
            sA[(c0 + 2) * LDT + r0] = a0v.z;
            sA[(c0 + 3) * LDT + r0] = a0v.w;
            sA[(c1 + 0) * LDT + r1] = a1v.x;
            sA[(c1 + 1) * LDT + r1] = a1v.y;
            sA[(c1 + 2) * LDT + r1] = a1v.z;
            sA[(c1 + 3) * LDT + r1] = a1v.w;
            sB[(c0 + 0) * LDT + r0] = b0v.x;
            sB[(c0 + 1) * LDT + r0] = b0v.y;
            sB[(c0 + 2) * LDT + r0] = b0v.z;
            sB[(c0 + 3) * LDT + r0] = b0v.w;
            sB[(c1 + 0) * LDT + r1] = b1v.x;
            sB[(c1 + 1) * LDT + r1] = b1v.y;
            sB[(c1 + 2) * LDT + r1] = b1v.z;
            sB[(c1 + 3) * LDT + r1] = b1v.w;
            __syncthreads();

            if (kc + KC < EDIM) {
                a0v = *(const float4*)(Ab0 + kc + KC);
                a1v = *(const float4*)(Ab1 + kc + KC);
                b0v = *(const float4*)(Bb0 + kc + KC);
                b1v = *(const float4*)(Bb1 + kc + KC);
            }

#pragma unroll 4
            for (int kk = 0; kk < KC; kk++) {
                const float* Ar = &sA[kk * LDT + ty * 8];
                float4 af0 = *(const float4*)(Ar);
                float4 af1 = *(const float4*)(Ar + 4);
                const unsigned long long* Br =
                    (const unsigned long long*)&sB[kk * LDT + tx * 8];
                unsigned long long bb0 = Br[0], bb1 = Br[1];
                unsigned long long bb2 = Br[2], bb3 = Br[3];
                float a[8] = {af0.x, af0.y, af0.z, af0.w,
                              af1.x, af1.y, af1.z, af1.w};
                unsigned long long ap[8];
#pragma unroll
                for (int i = 0; i < 8; i++) PACK_DUP(ap[i], a[i]);
#pragma unroll
                for (int i = 0; i < 8; i++) {
                    FMA2(acc[i * 4 + 0], ap[i], bb0);
                    FMA2(acc[i * 4 + 1], ap[i], bb1);
                    FMA2(acc[i * 4 + 2], ap[i], bb2);
                    FMA2(acc[i * 4 + 3], ap[i], bb3);
                }
            }
        }
        __syncthreads();
        // dump the 128x128 score chunk to smem
#pragma unroll
        for (int i = 0; i < 8; i++) {
            unsigned long long* dst =
                (unsigned long long*)&sS[(ty * 8 + i) * LDT + tx * 8];
            dst[0] = acc[i * 4 + 0];
            dst[1] = acc[i * 4 + 1];
            dst[2] = acc[i * 4 + 2];
            dst[3] = acc[i * 4 + 3];
        }
        __syncthreads();
        // per-token top-4 update (strict > keeps earlier index on ties,
        // matching jax.lax.top_k tie-breaking)
        if (tid < TT) {
            const float* rowp = &sS[tid * LDT];
#pragma unroll 4
            for (int j = 0; j < MT; j++) {
                float s = rowp[j];
                if (s > v3) {
                    int m = mb + j;
                    if (s > v1) {
                        if (s > v0) {
                            v3 = v2; i3 = i2; v2 = v1; i2 = i1;
                            v1 = v0; i1 = i0; v0 = s;  i0 = m;
                        } else {
                            v3 = v2; i3 = i2; v2 = v1; i2 = i1;
                            v1 = s;  i1 = m;
                        }
                    } else {
                        if (s > v2) { v3 = v2; i3 = i2; v2 = s; i2 = m; }
                        else        { v3 = s;  i3 = m; }
                    }
                }
            }
        }
        // next iteration's first __syncthreads() protects sS/sA reuse
    }

    if (tid < TT) {
        const int t = tb + tid;
        float e0 = 1.f;
        float e1 = expf(v1 - v0);
        float e2 = expf(v2 - v0);
        float e3 = expf(v3 - v0);
        float ssum = e0 + e1 + e2 + e3;
        const int base = t * (NSEC * TOPK) + n * TOPK;
        g_w[base + 0] = e0 / ssum;  g_ix[base + 0] = i0;
        g_w[base + 1] = e1 / ssum;  g_ix[base + 1] = i1;
        g_w[base + 2] = e2 / ssum;  g_ix[base + 2] = i2;
        g_w[base + 3] = e3 / ssum;  g_ix[base + 3] = i3;
    }
}

// ---------------------------------------------------------------------------
// K3: gather knowledge, matvec, sector mix, project, residual, LayerNorm
// grid: NTOK blocks, 128 threads (4 warps; warp w handles pick k=w)
// ---------------------------------------------------------------------------
__global__ __launch_bounds__(128) void k3_output(
    const float* __restrict__ knowledge,  // [N][M][KD][VD]
    const float* __restrict__ Wo,         // [VD][E]
    const float* __restrict__ bo,         // [E]
    const float* __restrict__ gamma,
    const float* __restrict__ beta,
    float* __restrict__ out)              // d_out base
{
    const int t    = blockIdx.x;
    const int tid  = threadIdx.x;
    const int lane = tid & 31;
    const int wid  = tid >> 5;

    __shared__ float q[KDIM];
    __shared__ float sd[NSEC];
    __shared__ float fpart[4][VDIM];
    __shared__ float fin[VDIM];
    __shared__ float rs[4], rs2[4];
    __shared__ float mv[2];

    if (tid < KDIM) q[tid] = g_tq[t * KDIM + tid];
    if (tid < NSEC) sd[tid] = out[(size_t)NTOK * EDIM + t * NSEC + tid];
    __syncthreads();

    // warp wid handles pick index k = wid across all 8 sectors; lane = v
    float facc = 0.f;
#pragma unroll
    for (int n = 0; n < NSEC; n++) {
        const int p  = t * (NSEC * TOPK) + n * TOPK + wid;
        const float wgt = g_w[p];
        const int   mi  = g_ix[p];
        const float* kn =
            knowledge + ((size_t)n * MTOT + mi) * (KDIM * VDIM);
        float r = 0.f;
#pragma unroll
        for (int d = 0; d < KDIM; d++)
            r += q[d] * kn[d * VDIM + lane];
        facc += sd[n] * wgt * r;
    }
    fpart[wid][lane] = facc;
    __syncthreads();
    if (tid < VDIM)
        fin[tid] = fpart[0][tid] + fpart[1][tid] + fpart[2][tid] + fpart[3][tid];
    __syncthreads();

    // proj + residual
    float4 accv = *(const float4*)&bo[tid * 4];
#pragma unroll
    for (int v = 0; v < VDIM; v++) {
        float fv = fin[v];
        float4 wv = *(const float4*)&Wo[v * EDIM + tid * 4];
        accv.x += fv * wv.x; accv.y += fv * wv.y;
        accv.z += fv * wv.z; accv.w += fv * wv.w;
    }
    float4 xv = *(const float4*)&g_xe[(size_t)t * EDIM + tid * 4];
    float4 h;
    h.x = xv.x + accv.x; h.y = xv.y + accv.y;
    h.z = xv.z + accv.z; h.w = xv.w + accv.w;

    // LayerNorm
    float s  = h.x + h.y + h.z + h.w;
    float s2 = h.x * h.x + h.y * h.y + h.z * h.z + h.w * h.w;
#pragma unroll
    for (int o = 16; o > 0; o >>= 1) {
        s  += __shfl_xor_sync(0xffffffffu, s,  o);
        s2 += __shfl_xor_sync(0xffffffffu, s2, o);
    }
    if (lane == 0) { rs[wid] = s; rs2[wid] = s2; }
    __syncthreads();
    if (tid == 0) {
        float S  = rs[0] + rs[1] + rs[2] + rs[3];
        float S2 = rs2[0] + rs2[1] + rs2[2] + rs2[3];
        float mu  = S  / (float)EDIM;
        float var = S2 / (float)EDIM - mu * mu;
        mv[0] = mu;
        mv[1] = rsqrtf(var + 1e-5f);
    }
    __syncthreads();
    const float mu = mv[0], rstd = mv[1];

    float4 gv = *(const float4*)&gamma[tid * 4];
    float4 bv = *(const float4*)&beta[tid * 4];
    float4 ov;
    ov.x = (h.x - mu) * rstd * gv.x + bv.x;
    ov.y = (h.y - mu) * rstd * gv.y + bv.y;
    ov.z = (h.z - mu) * rstd * gv.z + bv.z;
    ov.w = (h.w - mu) * rstd * gv.w + bv.w;
    *(float4*)&out[(size_t)t * EDIM + tid * 4] = ov;
}

// ---------------------------------------------------------------------------
extern "C" void kernel_launch(void* const* d_in, const int* in_sizes, int n_in,
                              void* d_out, int out_size)
{
    // input order per setup_inputs: x, top_k, emb, sector_keys, memory_keys,
    // knowledge, Wq, bq, Wo, bo, gamma, beta. top_k may or may not be
    // materialized as a size-1 input; detect it.
    const int off = (n_in >= 12 && in_sizes[1] == 1) ? 1 : 0;

    const int*   x      = (const int*)  d_in[0];
    const float* emb    = (const float*)d_in[1 + off];
    const float* skeys  = (const float*)d_in[2 + off];
    const float* mkeys  = (const float*)d_in[3 + off];
    const float* knowl  = (const float*)d_in[4 + off];
    const float* Wq     = (const float*)d_in[5 + off];
    const float* bq     = (const float*)d_in[6 + off];
    const float* Wo     = (const float*)d_in[7 + off];
    const float* bo     = (const float*)d_in[8 + off];
    const float* gamma  = (const float*)d_in[9 + off];
    const float* beta   = (const float*)d_in[10 + off];
    float* out = (float*)d_out;
    (void)out_size;

    cudaFuncSetAttribute(k2_scores,
                         cudaFuncAttributeMaxDynamicSharedMemorySize,
                         SMEM2_BYTES);

    k1_embed <<<NTOK, 128>>>(x, emb, skeys, Wq, bq, out + (size_t)NTOK * EDIM);
    k2_scores<<<dim3(NTOK / TT, NSEC), 256, SMEM2_BYTES>>>(mkeys);
    k3_output<<<NTOK, 128>>>(knowl, Wo, bo, gamma, beta, out);
}

// round 2
// speedup vs baseline: 1.0026x; 1.0026x over previous
#include <cuda_runtime.h>
#include <cuda_bf16.h>
#include <cstdint>
#include <cstddef>

// ---------------------------------------------------------------------------
// HierarchicalMemoryWorker — fused fp32 implementation (round 1)
//
// Shapes: B=2,S=1024 (T=2048 tokens), V=32000, E=512, N=8, M=2048, KD=VD=32, K=4
//
// K1: embed gather + sector softmax + token query
// K2: score GEMM (x_emb @ memory_keys^T) with streaming top-4 + weights
//     (uses fma.rn.f32x2 packed math: 2 MACs/instr -> 128 FMA/SM/cyc)
// K3: knowledge gather + matvec + sector mix + Wo proj + residual + LayerNorm
// ---------------------------------------------------------------------------

#define NTOK   2048
#define EDIM   512
#define NSEC   8
#define MTOT   2048
#define KDIM   32
#define VDIM   32
#define TOPK   4

// K2 tiling
#define TT   128      // token tile
#define MT   128      // memory chunk
#define KC   16       // k chunk
#define LDT  132      // smem row stride (floats), 16B-aligned, conflict-softened

#define SMEM2_FLOATS ((2*KC + TT) * LDT)
#define SMEM2_BYTES  (SMEM2_FLOATS * 4)   // 84480 bytes

// scratch (device globals: no allocation allowed)
__device__ float g_xe[NTOK * EDIM];        // 4 MB
__device__ float g_tq[NTOK * KDIM];        // 256 KB
__device__ float g_w [NTOK * NSEC * TOPK]; // 256 KB
__device__ int   g_ix[NTOK * NSEC * TOPK]; // 256 KB

// packed f32x2 helpers
#define PACK_DUP(d, f) asm("mov.b64 %0, {%1, %1};" : "=l"(d) : "r"(__float_as_uint(f)))
#define FMA2(c, a, b)  asm("fma.rn.f32x2 %0, %1, %2, %0;" : "+l"(c) : "l"(a), "l"(b))

// ---------------------------------------------------------------------------
// K1: per-token embed gather, sector scores->softmax, token query
// grid: NTOK blocks, 128 threads
// ---------------------------------------------------------------------------
__global__ __launch_bounds__(128) void k1_embed(
    const int* __restrict__ x,
    const float* __restrict__ emb,
    const float* __restrict__ skeys,   // [N][E]
    const float* __restrict__ Wq,      // [E][KD]
    const float* __restrict__ bq,      // [KD]
    float* __restrict__ outSD)         // [NTOK][N]
{
    const int t   = blockIdx.x;
    const int tid = threadIdx.x;
    const int lane = tid & 31;
    const int wid  = tid >> 5;

    __shared__ float se[EDIM];
    __shared__ float sred[NSEC][4];
    __shared__ float ssc[NSEC];

    const int xi = x[t];
    float4 ev = *(const float4*)&emb[(size_t)xi * EDIM + tid * 4];
    *(float4*)&g_xe[(size_t)t * EDIM + tid * 4] = ev;
    *(float4*)&se[tid * 4] = ev;

    float p[NSEC];
#pragma unroll
    for (int n = 0; n < NSEC; n++) {
        float4 kv = *(const float4*)&skeys[n * EDIM + tid * 4];
        p[n] = ev.x * kv.x + ev.y * kv.y + ev.z * kv.z + ev.w * kv.w;
    }
#pragma unroll
    for (int n = 0; n < NSEC; n++)
#pragma unroll
        for (int o = 16; o > 0; o >>= 1)
            p[n] += __shfl_xor_sync(0xffffffffu, p[n], o);
    if (lane == 0) {
#pragma unroll
        for (int n = 0; n < NSEC; n++) sred[n][wid] = p[n];
    }
    __syncthreads();
    if (tid == 0) {
        float s[NSEC];
        float mx = -1e30f;
#pragma unroll
        for (int n = 0; n < NSEC; n++) {
            s[n] = sred[n][0] + sred[n][1] + sred[n][2] + sred[n][3];
            mx = fmaxf(mx, s[n]);
        }
        float sum = 0.f;
#pragma unroll
        for (int n = 0; n < NSEC; n++) { s[n] = expf(s[n] - mx); sum += s[n]; }
#pragma unroll
        for (int n = 0; n < NSEC; n++) {
            float d = s[n] / sum;
            ssc[n] = d;
            outSD[t * NSEC + n] = d;
        }
    }
    __syncthreads();
    (void)ssc;

    // token query: 32 outputs
    if (tid < KDIM) {
        float acc = bq[tid];
#pragma unroll 8
        for (int j = 0; j < EDIM; j++)
            acc += se[j] * Wq[j * KDIM + tid];
        g_tq[t * KDIM + tid] = acc;
    }
}

// ---------------------------------------------------------------------------
// K2: score GEMM + streaming top-4
// grid: (NTOK/TT, NSEC), 256 threads
// thread (tx = tid&15, ty = tid>>4) computes an 8x8 (tok x mem) register tile
// as 8x4 f32x2 pairs.
// ---------------------------------------------------------------------------
__global__ __launch_bounds__(256, 1) void k2_scores(
    const float* __restrict__ mkeys)   // [N][M][E]
{
    extern __shared__ float sm[];
    float* sA = sm;                    // [KC][LDT]  (k-major, token minor)
    float* sB = sm + KC * LDT;         // [KC][LDT]  (k-major, mem minor)
    float* sS = sm + 2 * KC * LDT;     // [TT][LDT]  score tile

    const int tid = threadIdx.x;
    const int tb  = blockIdx.x * TT;
    const int n   = blockIdx.y;
    const int tx  = tid & 15;
    const int ty  = tid >> 4;

    // global load mapping: 512 float4 per tile, 2 per thread
    const int idx0 = tid, idx1 = tid + 256;
    const int r0 = idx0 >> 2, c0 = (idx0 & 3) * 4;
    const int r1 = idx1 >> 2, c1 = (idx1 & 3) * 4;

    const float* Ab0 = &g_xe[(size_t)(tb + r0) * EDIM + c0];
    const float* Ab1 = &g_xe[(size_t)(tb + r1) * EDIM + c1];
    const float* Bn  = mkeys + (size_t)n * MTOT * EDIM;

    // persistent top-4 state (tid < TT owns token tb+tid)
    float v0 = -1e30f, v1 = -1e30f, v2 = -1e30f, v3 = -1e30f;
    int   i0 = 0, i1 = 0, i2 = 0, i3 = 0;

    for (int mb = 0; mb < MTOT; mb += MT) {
        unsigned long long acc[32];
#pragma unroll
        for (int i = 0; i < 32; i++) acc[i] = 0ull;

        const float* Bb0 = Bn + (size_t)(mb + r0) * EDIM + c0;
        const float* Bb1 = Bn + (size_t)(mb + r1) * EDIM + c1;

        float4 a0v = *(const float4*)(Ab0);
        float4 a1v = *(const float4*)(Ab1);
        float4 b0v = *(const float4*)(Bb0);
        float4 b1v = *(const float4*)(Bb1);

        for (int kc = 0; kc < EDIM; kc += KC) {
            __syncthreads();   // previous compute / scan done
            // store prefetched regs to smem (transposed)
            sA[(c0 + 0) * LDT + r0] = a0v.x;
            sA[(c0 + 1) * LDT + r0] = a0v.y;
            sA[(c0 + 2) * LDT + r0] = a0v.z;
            sA[(c0 + 3) * LDT + r0] = a0v.w;
            sA[(c1 + 0) * LDT + r1] = a1v.x;
            sA[(c1 + 1) * LDT + r1] = a1v.y;
            sA[(c1 + 2) * LDT + r1] = a1v.z;
            sA[(c1 + 3) * LDT + r1] = a1v.w;
            sB[(c0 + 0) * LDT + r0] = b0v.x;
            sB[(c0 + 1) * LDT + r0] = b0v.y;
            sB[(c0 + 2) * LDT + r0] = b0v.z;
            sB[(c0 + 3) * LDT + r0] = b0v.w;
            sB[(c1 + 0) * LDT + r1] = b1v.x;
            sB[(c1 + 1) * LDT + r1] = b1v.y;
            sB[(c1 + 2) * LDT + r1] = b1v.z;
            sB[(c1 + 3) * LDT + r1] = b1v.w;
            __syncthreads();

            if (kc + KC < EDIM) {
                a0v = *(const float4*)(Ab0 + kc + KC);
                a1v = *(const float4*)(Ab1 + kc + KC);
                b0v = *(const float4*)(Bb0 + kc + KC);
                b1v = *(const float4*)(Bb1 + kc + KC);
            }

#pragma unroll 4
            for (int kk = 0; kk < KC; kk++) {
                const float* Ar = &sA[kk * LDT + ty * 8];
                float4 af0 = *(const float4*)(Ar);
                float4 af1 = *(const float4*)(Ar + 4);
                const unsigned long long* Br =
                    (const unsigned long long*)&sB[kk * LDT + tx * 8];
                unsigned long long bb0 = Br[0], bb1 = Br[1];
                unsigned long long bb2 = Br[2], bb3 = Br[3];
                float a[8] = {af0.x, af0.y, af0.z, af0.w,
                              af1.x, af1.y, af1.z, af1.w};
                unsigned long long ap[8];
#pragma unroll
                for (int i = 0; i < 8; i++) PACK_DUP(ap[i], a[i]);
#pragma unroll
                for (int i = 0; i < 8; i++) {
                    FMA2(acc[i * 4 + 0], ap[i], bb0);
                    FMA2(acc[i * 4 + 1], ap[i], bb1);
                    FMA2(acc[i * 4 + 2], ap[i], bb2);
                    FMA2(acc[i * 4 + 3], ap[i], bb3);
                }
            }
        }
        __syncthreads();
        // dump the 128x128 score chunk to smem
#pragma unroll
        for (int i = 0; i < 8; i++) {
            unsigned long long* dst =
                (unsigned long long*)&sS[(ty * 8 + i) * LDT + tx * 8];
            dst[0] = acc[i * 4 + 0];
            dst[1] = acc[i * 4 + 1];
            dst[2] = acc[i * 4 + 2];
            dst[3] = acc[i * 4 + 3];
        }
        __syncthreads();
        // per-token top-4 update (strict > keeps earlier index on ties,
        // matching jax.lax.top_k tie-breaking)
        if (tid < TT) {
            const float* rowp = &sS[tid * LDT];
#pragma unroll 4
            for (int j = 0; j < MT; j++) {
                float s = rowp[j];
                if (s > v3) {
                    int m = mb + j;
                    if (s > v1) {
                        if (s > v0) {
                            v3 = v2; i3 = i2; v2 = v1; i2 = i1;
                            v1 = v0; i1 = i0; v0 = s;  i0 = m;
                        } else {
                            v3 = v2; i3 = i2; v2 = v1; i2 = i1;
                            v1 = s;  i1 = m;
                        }
                    } else {
                        if (s > v2) { v3 = v2; i3 = i2; v2 = s; i2 = m; }
                        else        { v3 = s;  i3 = m; }
                    }
                }
            }
        }
        // next iteration's first __syncthreads() protects sS/sA reuse
    }

    if (tid < TT) {
        const int t = tb + tid;
        float e0 = 1.f;
        float e1 = expf(v1 - v0);
        float e2 = expf(v2 - v0);
        float e3 = expf(v3 - v0);
        float ssum = e0 + e1 + e2 + e3;
        const int base = t * (NSEC * TOPK) + n * TOPK;
        g_w[base + 0] = e0 / ssum;  g_ix[base + 0] = i0;
        g_w[base + 1] = e1 / ssum;  g_ix[base + 1] = i1;
        g_w[base + 2] = e2 / ssum;  g_ix[base + 2] = i2;
        g_w[base + 3] = e3 / ssum;  g_ix[base + 3] = i3;
    }
}

// ---------------------------------------------------------------------------
// K3: gather knowledge, matvec, sector mix, project, residual, LayerNorm
// grid: NTOK blocks, 128 threads (4 warps; warp w handles pick k=w)
// ---------------------------------------------------------------------------
__global__ __launch_bounds__(128) void k3_output(
    const float* __restrict__ knowledge,  // [N][M][KD][VD]
    const float* __restrict__ Wo,         // [VD][E]
    const float* __restrict__ bo,         // [E]
    const float* __restrict__ gamma,
    const float* __restrict__ beta,
    float* __restrict__ out)              // d_out base
{
    const int t    = blockIdx.x;
    const int tid  = threadIdx.x;
    const int lane = tid & 31;
    const int wid  = tid >> 5;

    __shared__ float q[KDIM];
    __shared__ float sd[NSEC];
    __shared__ float fpart[4][VDIM];
    __shared__ float fin[VDIM];
    __shared__ float rs[4], rs2[4];
    __shared__ float mv[2];

    if (tid < KDIM) q[tid] = g_tq[t * KDIM + tid];
    if (tid < NSEC) sd[tid] = out[(size_t)NTOK * EDIM + t * NSEC + tid];
    __syncthreads();

    // warp wid handles pick index k = wid across all 8 sectors; lane = v
    float facc = 0.f;
#pragma unroll
    for (int n = 0; n < NSEC; n++) {
        const int p  = t * (NSEC * TOPK) + n * TOPK + wid;
        const float wgt = g_w[p];
        const int   mi  = g_ix[p];
        const float* kn =
            knowledge + ((size_t)n * MTOT + mi) * (KDIM * VDIM);
        float r = 0.f;
#pragma unroll
        for (int d = 0; d < KDIM; d++)
            r += q[d] * kn[d * VDIM + lane];
        facc += sd[n] * wgt * r;
    }
    fpart[wid][lane] = facc;
    __syncthreads();
    if (tid < VDIM)
        fin[tid] = fpart[0][tid] + fpart[1][tid] + fpart[2][tid] + fpart[3][tid];
    __syncthreads();

    // proj + residual
    float4 accv = *(const float4*)&bo[tid * 4];
#pragma unroll
    for (int v = 0; v < VDIM; v++) {
        float fv = fin[v];
        float4 wv = *(const float4*)&Wo[v * EDIM + tid * 4];
        accv.x += fv * wv.x; accv.y += fv * wv.y;
        accv.z += fv * wv.z; accv.w += fv * wv.w;
    }
    float4 xv = *(const float4*)&g_xe[(size_t)t * EDIM + tid * 4];
    float4 h;
    h.x = xv.x + accv.x; h.y = xv.y + accv.y;
    h.z = xv.z + accv.z; h.w = xv.w + accv.w;

    // LayerNorm
    float s  = h.x + h.y + h.z + h.w;
    float s2 = h.x * h.x + h.y * h.y + h.z * h.z + h.w * h.w;
#pragma unroll
    for (int o = 16; o > 0; o >>= 1) {
        s  += __shfl_xor_sync(0xffffffffu, s,  o);
        s2 += __shfl_xor_sync(0xffffffffu, s2, o);
    }
    if (lane == 0) { rs[wid] = s; rs2[wid] = s2; }
    __syncthreads();
    if (tid == 0) {
        float S  = rs[0] + rs[1] + rs[2] + rs[3];
        float S2 = rs2[0] + rs2[1] + rs2[2] + rs2[3];
        float mu  = S  / (float)EDIM;
        float var = S2 / (float)EDIM - mu * mu;
        mv[0] = mu;
        mv[1] = rsqrtf(var + 1e-5f);
    }
    __syncthreads();
    const float mu = mv[0], rstd = mv[1];

    float4 gv = *(const float4*)&gamma[tid * 4];
    float4 bv = *(const float4*)&beta[tid * 4];
    float4 ov;
    ov.x = (h.x - mu) * rstd * gv.x + bv.x;
    ov.y = (h.y - mu) * rstd * gv.y + bv.y;
    ov.z = (h.z - mu) * rstd * gv.z + bv.z;
    ov.w = (h.w - mu) * rstd * gv.w + bv.w;
    *(float4*)&out[(size_t)t * EDIM + tid * 4] = ov;
}

// ---------------------------------------------------------------------------
extern "C" void kernel_launch(void* const* d_in, const int* in_sizes, int n_in,
                              void* d_out, int out_size)
{
    // input order per setup_inputs: x, top_k, emb, sector_keys, memory_keys,
    // knowledge, Wq, bq, Wo, bo, gamma, beta. top_k may or may not be
    // materialized as a size-1 input; detect it.
    const int off = (n_in >= 12 && in_sizes[1] == 1) ? 1 : 0;

    const int*   x      = (const int*)  d_in[0];
    const float* emb    = (const float*)d_in[1 + off];
    const float* skeys  = (const float*)d_in[2 + off];
    const float* mkeys  = (const float*)d_in[3 + off];
    const float* knowl  = (const float*)d_in[4 + off];
    const float* Wq     = (const float*)d_in[5 + off];
    const float* bq     = (const float*)d_in[6 + off];
    const float* Wo     = (const float*)d_in[7 + off];
    const float* bo     = (const float*)d_in[8 + off];
    const float* gamma  = (const float*)d_in[9 + off];
    const float* beta   = (const float*)d_in[10 + off];
    float* out = (float*)d_out;
    (void)out_size;

    cudaFuncSetAttribute(k2_scores,
                         cudaFuncAttributeMaxDynamicSharedMemorySize,
                         SMEM2_BYTES);

    k1_embed <<<NTOK, 128>>>(x, emb, skeys, Wq, bq, out + (size_t)NTOK * EDIM);
    k2_scores<<<dim3(NTOK / TT, NSEC), 256, SMEM2_BYTES>>>(mkeys);
    k3_output<<<NTOK, 128>>>(knowl, Wo, bo, gamma, beta, out);
}

// round 5
// speedup vs baseline: 3.0203x; 3.0125x over previous
#include <cuda_runtime.h>
#include <cuda_bf16.h>
#include <cstdint>
#include <cstddef>

// ---------------------------------------------------------------------------
// HierarchicalMemoryWorker — mma.sync bf16 score GEMM + exact fp32 rerank
// (tcgen05 unavailable: harness ptxas target is plain sm_100)
// T=2048 tokens, E=512, N=8 sectors, M=2048, KD=VD=32, top-4
// R5 fix: mkb_conv grid was 4x too large (OOB read -> illegal memory access)
// ---------------------------------------------------------------------------

#define NTOK 2048
#define EDIM 512
#define NSEC 8
#define MTOT 2048
#define KDIM 32
#define VDIM 32

// ---- k2 smem layout ----
#define SA_STRIDE 520                      // bf16 elems/row (1040 B)
#define SB_STRIDE 72                       // bf16 elems/row (144 B)
#define SS_STRIDE 136                      // bf16 elems/row (272 B)
#define SA_BYTES  (128 * 1040)             // 133120
#define SB_BYTES  (128 * 144)              // 18432 per buffer
#define SS_OFF    (SA_BYTES + 2 * SB_BYTES)
#define SMEM2     (SS_OFF + 128 * 272)     // 204800

// ---- device scratch (no allocation allowed) ----
__device__ float g_xe[NTOK * EDIM];
__device__ float g_tq[NTOK * KDIM];
__device__ float g_w [NTOK * NSEC * 4];
__device__ int   g_ix[NTOK * NSEC * 4];
__device__ __nv_bfloat16 g_xeb[NTOK * EDIM];          // 2 MB bf16 x_emb
__device__ __nv_bfloat16 g_mkb[NSEC * MTOT * EDIM];   // 16 MB bf16 memory_keys

// ---- helpers ----
__device__ __forceinline__ uint32_t smem_u32(const void* p) {
    uint32_t a;
    asm("{ .reg .u64 t; cvta.to.shared.u64 t, %1; cvt.u32.u64 %0, t; }"
        : "=r"(a) : "l"(p));
    return a;
}
#define CP16(d, s) asm volatile("cp.async.ca.shared.global [%0], [%1], 16;" :: "r"(d), "l"(s))
#define CPCOMMIT() asm volatile("cp.async.commit_group;" ::: "memory")
#define CPWAIT1()  asm volatile("cp.async.wait_group 1;" ::: "memory")
#define CPWAIT0()  asm volatile("cp.async.wait_group 0;" ::: "memory")

#define LDM_X4(r0, r1, r2, r3, a) \
    asm volatile("ldmatrix.sync.aligned.m8n8.x4.shared.b16 {%0,%1,%2,%3}, [%4];" \
        : "=r"(r0), "=r"(r1), "=r"(r2), "=r"(r3) : "r"(a))

#define MMA16816(c0, c1, c2, c3, a0, a1, a2, a3, b0, b1) \
    asm volatile("mma.sync.aligned.m16n8k16.row.col.f32.bf16.bf16.f32 " \
        "{%0,%1,%2,%3}, {%4,%5,%6,%7}, {%8,%9}, {%0,%1,%2,%3};" \
        : "+f"(c0), "+f"(c1), "+f"(c2), "+f"(c3) \
        : "r"(a0), "r"(a1), "r"(a2), "r"(a3), "r"(b0), "r"(b1))

// ---------------------------------------------------------------------------
// k1: embed gather + sector softmax + fp32/bf16 x_emb
// ---------------------------------------------------------------------------
__global__ __launch_bounds__(128) void k1_embed(
    const int* __restrict__ x, const float* __restrict__ emb,
    const float* __restrict__ skeys, float* __restrict__ outSD)
{
    const int t = blockIdx.x, tid = threadIdx.x;
    const int lane = tid & 31, wid = tid >> 5;
    __shared__ float sred[NSEC][4];

    const int xi = x[t];
    float4 ev = *(const float4*)&emb[(size_t)xi * EDIM + tid * 4];
    *(float4*)&g_xe[(size_t)t * EDIM + tid * 4] = ev;
    {
        __nv_bfloat162 p0 = __floats2bfloat162_rn(ev.x, ev.y);
        __nv_bfloat162 p1 = __floats2bfloat162_rn(ev.z, ev.w);
        uint2 u; u.x = *(uint32_t*)&p0; u.y = *(uint32_t*)&p1;
        *(uint2*)&g_xeb[(size_t)t * EDIM + tid * 4] = u;
    }

    float p[NSEC];
#pragma unroll
    for (int n = 0; n < NSEC; n++) {
        float4 kv = *(const float4*)&skeys[n * EDIM + tid * 4];
        p[n] = ev.x*kv.x + ev.y*kv.y + ev.z*kv.z + ev.w*kv.w;
    }
#pragma unroll
    for (int n = 0; n < NSEC; n++)
#pragma unroll
        for (int o = 16; o > 0; o >>= 1)
            p[n] += __shfl_xor_sync(0xffffffffu, p[n], o);
    if (lane == 0)
#pragma unroll
        for (int n = 0; n < NSEC; n++) sred[n][wid] = p[n];
    __syncthreads();
    if (tid == 0) {
        float s[NSEC], mx = -1e30f, sum = 0.f;
#pragma unroll
        for (int n = 0; n < NSEC; n++) {
            s[n] = sred[n][0] + sred[n][1] + sred[n][2] + sred[n][3];
            mx = fmaxf(mx, s[n]);
        }
#pragma unroll
        for (int n = 0; n < NSEC; n++) { s[n] = expf(s[n] - mx); sum += s[n]; }
#pragma unroll
        for (int n = 0; n < NSEC; n++) outSD[t * NSEC + n] = s[n] / sum;
    }
}

// ---------------------------------------------------------------------------
// mkb_conv: memory_keys fp32 -> bf16 linear (8 elems / thread)
// total elems = NSEC*MTOT*EDIM = 8388608; /8/256 = 4096 blocks
// ---------------------------------------------------------------------------
__global__ __launch_bounds__(256) void mkb_conv(const float* __restrict__ mkeys)
{
    const size_t gi = (size_t)blockIdx.x * 256 + threadIdx.x;
    const float4* s = (const float4*)mkeys + gi * 2;
    float4 a = s[0], b = s[1];
    __nv_bfloat162 p0 = __floats2bfloat162_rn(a.x, a.y);
    __nv_bfloat162 p1 = __floats2bfloat162_rn(a.z, a.w);
    __nv_bfloat162 p2 = __floats2bfloat162_rn(b.x, b.y);
    __nv_bfloat162 p3 = __floats2bfloat162_rn(b.z, b.w);
    uint4 u;
    u.x = *(uint32_t*)&p0; u.y = *(uint32_t*)&p1;
    u.z = *(uint32_t*)&p2; u.w = *(uint32_t*)&p3;
    ((uint4*)g_mkb)[gi] = u;
}

// ---------------------------------------------------------------------------
// k1b: token query GEMM  tq[T,32] = xe[T,512] @ Wq[512,32] + bq
// ---------------------------------------------------------------------------
#define XSTR 68
__global__ __launch_bounds__(256) void k1b_tq(
    const float* __restrict__ Wq, const float* __restrict__ bq)
{
    extern __shared__ float s1b[];
    float* sWq = s1b;                   // 16384 floats
    float* sxe = s1b + EDIM * KDIM;     // 32 * XSTR
    const int tid = threadIdx.x, tb = blockIdx.x * 32;
    const int row = tid & 31, h = tid >> 5;

    const float4* Wq4 = (const float4*)Wq;
#pragma unroll
    for (int i = 0; i < 16; i++)
        ((float4*)sWq)[i * 256 + tid] = Wq4[i * 256 + tid];

    float4 acc = *(const float4*)&bq[h * 4];
    for (int kc = 0; kc < EDIM; kc += 64) {
        __syncthreads();
        {
            const int lr = tid >> 3, lk = (tid & 7) * 8;
            const float* src = &g_xe[(size_t)(tb + lr) * EDIM + kc + lk];
            float4 a = *(const float4*)src, b = *(const float4*)(src + 4);
            float* d = &sxe[lr * XSTR + lk];
            d[0]=a.x; d[1]=a.y; d[2]=a.z; d[3]=a.w;
            d[4]=b.x; d[5]=b.y; d[6]=b.z; d[7]=b.w;
        }
        __syncthreads();
#pragma unroll 8
        for (int k = 0; k < 64; k++) {
            float a = sxe[row * XSTR + k];
            float4 wv = *(const float4*)&sWq[(kc + k) * KDIM + h * 4];
            acc.x += a * wv.x; acc.y += a * wv.y;
            acc.z += a * wv.z; acc.w += a * wv.w;
        }
    }
    *(float4*)&g_tq[(size_t)(tb + row) * KDIM + h * 4] = acc;
}

// ---------------------------------------------------------------------------
// k2: mma.sync bf16 score GEMM + streaming top-8 + exact fp32 rerank
// grid (16, 8), 256 threads = 8 warps (2 tokHalf x 4 memQuarter)
// ---------------------------------------------------------------------------
__global__ __launch_bounds__(256, 1) void k2_scores(const float* __restrict__ mkeys)
{
    extern __shared__ unsigned char sm2[];
    __nv_bfloat16* sS = (__nv_bfloat16*)(sm2 + SS_OFF);
    __shared__ int scand[128 * 8];

    const int tid = threadIdx.x, wid = tid >> 5, lane = tid & 31;
    const int tt = blockIdx.x, n = blockIdx.y, tb = tt * 128;
    const int warpM = wid & 1, warpN = wid >> 1;

    const uint32_t aAddr = smem_u32(sm2);
    const uint32_t bAddr0 = aAddr + SA_BYTES;

    // ---- A: 128 x 512 bf16 -> smem (padded rows), one cp.async burst ----
    {
        const __nv_bfloat16* Asrc = g_xeb + (size_t)tb * EDIM;
#pragma unroll
        for (int it = 0; it < 32; it++) {
            int idx = it * 256 + tid;       // 0..8191
            int r = idx >> 6, c = idx & 63;
            CP16(aAddr + r * 1040 + c * 16, Asrc + (size_t)r * EDIM + c * 8);
        }
        CPCOMMIT();
    }

    const __nv_bfloat16* Bn = g_mkb + (size_t)n * MTOT * EDIM;
    auto issueB = [&](int ck, int buf) {
        const int chunk = ck >> 3, kb = ck & 7;
        const __nv_bfloat16* src = Bn + (size_t)(chunk * 128) * EDIM + kb * 64;
        const uint32_t dst = bAddr0 + buf * SB_BYTES;
#pragma unroll
        for (int it = 0; it < 4; it++) {
            int idx = it * 256 + tid;       // 0..1023
            int r = idx >> 3, c = idx & 7;
            CP16(dst + r * 144 + c * 16, src + (size_t)r * EDIM + c * 8);
        }
        CPCOMMIT();
    };
    issueB(0, 0);

    // top-8 state (tid < 128 owns token tb+tid)
    float vt[8]; int ixt[8];
#pragma unroll
    for (int i = 0; i < 8; i++) { vt[i] = -3e38f; ixt[i] = 0; }

    float acc[4][4][4];
#pragma unroll
    for (int i = 0; i < 4; i++)
#pragma unroll
        for (int j = 0; j < 4; j++)
#pragma unroll
            for (int r = 0; r < 4; r++) acc[i][j][r] = 0.f;

    // ldmatrix lane address components
    const int aRow = warpM * 64 + (lane & 15);          // + i*16
    const int aKof = (lane >> 4) * 8;                   // + k0
    const int bRow = warpN * 32 + (lane & 7) + (lane >> 4) * 8;  // + jp*16
    const int bKof = ((lane >> 3) & 1) * 8;             // + k0

    for (int ck = 0; ck < 128; ck++) {
        const int buf = ck & 1, kb = ck & 7;
        if (ck + 1 < 128) { issueB(ck + 1, buf ^ 1); CPWAIT1(); }
        else              { CPWAIT0(); }
        __syncthreads();

        const uint32_t bBuf = bAddr0 + buf * SB_BYTES;
#pragma unroll
        for (int s = 0; s < 4; s++) {
            const int k0 = s * 16;
            uint32_t a[4][4];
#pragma unroll
            for (int i = 0; i < 4; i++) {
                uint32_t ad = aAddr + (aRow + i * 16) * 1040
                            + (kb * 64 + k0 + aKof) * 2;
                LDM_X4(a[i][0], a[i][1], a[i][2], a[i][3], ad);
            }
            uint32_t b[4][2];
#pragma unroll
            for (int jp = 0; jp < 2; jp++) {
                uint32_t bd = bBuf + (bRow + jp * 16) * 144 + (k0 + bKof) * 2;
                LDM_X4(b[jp*2][0], b[jp*2][1], b[jp*2+1][0], b[jp*2+1][1], bd);
            }
#pragma unroll
            for (int i = 0; i < 4; i++)
#pragma unroll
                for (int j = 0; j < 4; j++)
                    MMA16816(acc[i][j][0], acc[i][j][1], acc[i][j][2], acc[i][j][3],
                             a[i][0], a[i][1], a[i][2], a[i][3],
                             b[j][0], b[j][1]);
        }
        __syncthreads();

        if (kb == 7) {
            // ---- epilogue: dump scores (bf16) + streaming top-8 scan ----
            const int row0 = warpM * 64 + (lane >> 2);
            const int col0 = warpN * 32 + (lane & 3) * 2;
#pragma unroll
            for (int i = 0; i < 4; i++)
#pragma unroll
                for (int j = 0; j < 4; j++) {
                    __nv_bfloat162 lo =
                        __floats2bfloat162_rn(acc[i][j][0], acc[i][j][1]);
                    __nv_bfloat162 hi =
                        __floats2bfloat162_rn(acc[i][j][2], acc[i][j][3]);
                    *(uint32_t*)&sS[(row0 + i * 16) * SS_STRIDE + col0 + j * 8] =
                        *(uint32_t*)&lo;
                    *(uint32_t*)&sS[(row0 + i * 16 + 8) * SS_STRIDE + col0 + j * 8] =
                        *(uint32_t*)&hi;
                    acc[i][j][0] = acc[i][j][1] = acc[i][j][2] = acc[i][j][3] = 0.f;
                }
            __syncthreads();
            if (tid < 128) {
                const int mbase = (ck >> 3) * 128;
                const __nv_bfloat16* srow = sS + tid * SS_STRIDE;
#pragma unroll 2
                for (int c0 = 0; c0 < 128; c0 += 8) {
                    uint4 u = *(const uint4*)(srow + c0);
                    const __nv_bfloat162* hp = (const __nv_bfloat162*)&u;
#pragma unroll
                    for (int p = 0; p < 4; p++) {
                        float f0 = __bfloat162float(__low2bfloat16(hp[p]));
                        float f1 = __bfloat162float(__high2bfloat16(hp[p]));
#pragma unroll
                        for (int h = 0; h < 2; h++) {
                            float sv = h ? f1 : f0;
                            if (sv > vt[7]) {
                                vt[7] = sv; ixt[7] = mbase + c0 + p * 2 + h;
#pragma unroll
                                for (int q = 7; q > 0; q--) {
                                    if (vt[q] > vt[q-1]) {
                                        float a2 = vt[q]; vt[q] = vt[q-1]; vt[q-1] = a2;
                                        int b2 = ixt[q]; ixt[q] = ixt[q-1]; ixt[q-1] = b2;
                                    }
                                }
                            }
                        }
                    }
                }
            }
        }
    }

    if (tid < 128)
#pragma unroll
        for (int c = 0; c < 8; c++) scand[tid * 8 + c] = ixt[c];
    __syncthreads();

    // ---- exact fp32 rerank: 8 warps x 16 tokens, lane-split over E ----
    for (int ti = 0; ti < 16; ti++) {
        const int tl = wid * 16 + ti, t = tb + tl;
        const float* xr = g_xe + (size_t)t * EDIM + lane * 16;
        float4 x0 = *(const float4*)xr,       x1 = *(const float4*)(xr + 4);
        float4 x2 = *(const float4*)(xr + 8), x3 = *(const float4*)(xr + 12);
        float sc[8]; int ci[8];
#pragma unroll
        for (int c = 0; c < 8; c++) {
            ci[c] = scand[tl * 8 + c];
            const float* mr =
                mkeys + ((size_t)n * MTOT + ci[c]) * EDIM + lane * 16;
            float4 m0 = *(const float4*)mr,       m1 = *(const float4*)(mr + 4);
            float4 m2 = *(const float4*)(mr + 8), m3 = *(const float4*)(mr + 12);
            float d =            x0.x*m0.x;  d = fmaf(x0.y, m0.y, d);
            d = fmaf(x0.z, m0.z, d); d = fmaf(x0.w, m0.w, d);
            d = fmaf(x1.x, m1.x, d); d = fmaf(x1.y, m1.y, d);
            d = fmaf(x1.z, m1.z, d); d = fmaf(x1.w, m1.w, d);
            d = fmaf(x2.x, m2.x, d); d = fmaf(x2.y, m2.y, d);
            d = fmaf(x2.z, m2.z, d); d = fmaf(x2.w, m2.w, d);
            d = fmaf(x3.x, m3.x, d); d = fmaf(x3.y, m3.y, d);
            d = fmaf(x3.z, m3.z, d); d = fmaf(x3.w, m3.w, d);
#pragma unroll
            for (int o = 16; o > 0; o >>= 1)
                d += __shfl_xor_sync(0xffffffffu, d, o);
            sc[c] = d;
        }
        unsigned used = 0;
        float w4[4]; int id4[4];
#pragma unroll
        for (int s4 = 0; s4 < 4; s4++) {
            float bv = -3e38f; int bi = 0x7fffffff, bc = 0;
#pragma unroll
            for (int c = 0; c < 8; c++) {
                if (!((used >> c) & 1)) {
                    bool bet = (sc[c] > bv) || (sc[c] == bv && ci[c] < bi);
                    if (bet) { bv = sc[c]; bi = ci[c]; bc = c; }
                }
            }
            used |= 1u << bc; w4[s4] = bv; id4[s4] = bi;
        }
        if (lane == 0) {
            float e1 = expf(w4[1] - w4[0]);
            float e2 = expf(w4[2] - w4[0]);
            float e3 = expf(w4[3] - w4[0]);
            float ss = 1.f + e1 + e2 + e3;
            const int base = t * (NSEC * 4) + n * 4;
            g_w[base + 0] = 1.f / ss; g_ix[base + 0] = id4[0];
            g_w[base + 1] = e1 / ss;  g_ix[base + 1] = id4[1];
            g_w[base + 2] = e2 / ss;  g_ix[base + 2] = id4[2];
            g_w[base + 3] = e3 / ss;  g_ix[base + 3] = id4[3];
        }
    }
}

// ---------------------------------------------------------------------------
// k3: knowledge gather + matvec + sector mix + proj + residual + LayerNorm
// ---------------------------------------------------------------------------
__global__ __launch_bounds__(128) void k3_output(
    const float* __restrict__ knowledge, const float* __restrict__ Wo,
    const float* __restrict__ bo, const float* __restrict__ gamma,
    const float* __restrict__ beta, float* __restrict__ out)
{
    const int t = blockIdx.x, tid = threadIdx.x;
    const int lane = tid & 31, wid = tid >> 5;

    __shared__ float q[KDIM];
    __shared__ float sd[NSEC];
    __shared__ float fpart[4][VDIM];
    __shared__ float fin[VDIM];
    __shared__ float rs[4], rs2[4];
    __shared__ float mv[2];

    if (tid < KDIM) q[tid] = g_tq[t * KDIM + tid];
    if (tid < NSEC) sd[tid] = out[(size_t)NTOK * EDIM + t * NSEC + tid];
    __syncthreads();

    float facc = 0.f;
#pragma unroll
    for (int n = 0; n < NSEC; n++) {
        const int p = t * (NSEC * 4) + n * 4 + wid;
        const float wgt = g_w[p];
        const int   mi  = g_ix[p];
        const float* kn = knowledge + ((size_t)n * MTOT + mi) * (KDIM * VDIM);
        float r = 0.f;
#pragma unroll
        for (int d = 0; d < KDIM; d++)
            r += q[d] * kn[d * VDIM + lane];
        facc += sd[n] * wgt * r;
    }
    fpart[wid][lane] = facc;
    __syncthreads();
    if (tid < VDIM)
        fin[tid] = fpart[0][tid] + fpart[1][tid] + fpart[2][tid] + fpart[3][tid];
    __syncthreads();

    float4 accv = *(const float4*)&bo[tid * 4];
#pragma unroll
    for (int v = 0; v < VDIM; v++) {
        float fv = fin[v];
        float4 wv = *(const float4*)&Wo[v * EDIM + tid * 4];
        accv.x += fv * wv.x; accv.y += fv * wv.y;
        accv.z += fv * wv.z; accv.w += fv * wv.w;
    }
    float4 xv = *(const float4*)&g_xe[(size_t)t * EDIM + tid * 4];
    float4 h;
    h.x = xv.x + accv.x; h.y = xv.y + accv.y;
    h.z = xv.z + accv.z; h.w = xv.w + accv.w;

    float s  = h.x + h.y + h.z + h.w;
    float s2 = h.x*h.x + h.y*h.y + h.z*h.z + h.w*h.w;
#pragma unroll
    for (int o = 16; o > 0; o >>= 1) {
        s  += __shfl_xor_sync(0xffffffffu, s,  o);
        s2 += __shfl_xor_sync(0xffffffffu, s2, o);
    }
    if (lane == 0) { rs[wid] = s; rs2[wid] = s2; }
    __syncthreads();
    if (tid == 0) {
        float S  = rs[0] + rs[1] + rs[2] + rs[3];
        float S2 = rs2[0] + rs2[1] + rs2[2] + rs2[3];
        float mu  = S / (float)EDIM;
        float var = S2 / (float)EDIM - mu * mu;
        mv[0] = mu; mv[1] = rsqrtf(var + 1e-5f);
    }
    __syncthreads();
    const float mu = mv[0], rstd = mv[1];

    float4 gv = *(const float4*)&gamma[tid * 4];
    float4 bv = *(const float4*)&beta[tid * 4];
    float4 ov;
    ov.x = (h.x - mu) * rstd * gv.x + bv.x;
    ov.y = (h.y - mu) * rstd * gv.y + bv.y;
    ov.z = (h.z - mu) * rstd * gv.z + bv.z;
    ov.w = (h.w - mu) * rstd * gv.w + bv.w;
    *(float4*)&out[(size_t)t * EDIM + tid * 4] = ov;
}

// ---------------------------------------------------------------------------
extern "C" void kernel_launch(void* const* d_in, const int* in_sizes, int n_in,
                              void* d_out, int out_size)
{
    const int off = (n_in >= 12 && in_sizes[1] == 1) ? 1 : 0;

    const int*   x     = (const int*)  d_in[0];
    const float* emb   = (const float*)d_in[1 + off];
    const float* skeys = (const float*)d_in[2 + off];
    const float* mkeys = (const float*)d_in[3 + off];
    const float* knowl = (const float*)d_in[4 + off];
    const float* Wq    = (const float*)d_in[5 + off];
    const float* bq    = (const float*)d_in[6 + off];
    const float* Wo    = (const float*)d_in[7 + off];
    const float* bo    = (const float*)d_in[8 + off];
    const float* gamma = (const float*)d_in[9 + off];
    const float* beta  = (const float*)d_in[10 + off];
    float* out = (float*)d_out;
    (void)out_size;

    cudaFuncSetAttribute(k2_scores,
                         cudaFuncAttributeMaxDynamicSharedMemorySize, SMEM2);
    cudaFuncSetAttribute(k1b_tq,
                         cudaFuncAttributeMaxDynamicSharedMemorySize,
                         (EDIM * KDIM + 32 * XSTR) * 4);

    k1_embed<<<NTOK, 128>>>(x, emb, skeys, out + (size_t)NTOK * EDIM);
    // NSEC*MTOT*EDIM / (8 elems/thread) / 256 threads = 4096 blocks
    mkb_conv<<<4096, 256>>>(mkeys);
    k1b_tq  <<<64, 256, (EDIM * KDIM + 32 * XSTR) * 4>>>(Wq, bq);
    k2_scores<<<dim3(16, 8), 256, SMEM2>>>(mkeys);
    k3_output<<<NTOK, 128>>>(knowl, Wo, bo, gamma, beta, out);
}